// round 15
// baseline (speedup 1.0000x reference)
#include <cuda_runtime.h>
#include <cstdint>

#define NN 100000
#define NE 3200000
#define NF 128
#define NH 16
#define CAP 128

// ---------------- scratch (static device memory; no allocations) ----------------
__device__ int   g_cnt[NN];            // in-degree / CSR fill counter
__device__ int   g_csr[NN * CAP];      // padded CSR: rows (sources) per dst node
__device__ float g_g1[NN * NH];        // g1 = (x@W1)*dinv   [N,16]
__device__ float g_g2[NN];             // g2 = (h1@W2)*dinv  [N]

// Build padded CSR keyed by destination; g_cnt becomes the in-degree.
// 4 edges per thread, vectorized index loads. Edge dtype (int32 vs int64)
// detected inline: high 32-bit words of the first 32 int64 slots are all zero
// iff the data is int64 (node ids < 100000; if int32, those words are random
// node ids -> P(all 32 == 0) ~ 1e-160).
__global__ void k_build(const void* __restrict__ ep) {
    int lane = threadIdx.x & 31;
    const unsigned int* e32 = (const unsigned int*)ep;
    int is64 = __all_sync(0xffffffffu, e32[2 * lane + 1] == 0u);

    int t = blockIdx.x * 256 + threadIdx.x;     // t in [0, NE/4)
    int r[4], c[4];
    if (is64) {
        const longlong2* p = (const longlong2*)ep;
        longlong2 a = __ldg(p + 2 * t);
        longlong2 b = __ldg(p + 2 * t + 1);
        longlong2 d = __ldg(p + (NE >> 1) + 2 * t);
        longlong2 e = __ldg(p + (NE >> 1) + 2 * t + 1);
        r[0] = (int)a.x; r[1] = (int)a.y; r[2] = (int)b.x; r[3] = (int)b.y;
        c[0] = (int)d.x; c[1] = (int)d.y; c[2] = (int)e.x; c[3] = (int)e.y;
    } else {
        const int4* p = (const int4*)ep;
        int4 a = __ldg(p + t);
        int4 d = __ldg(p + (NE >> 2) + t);
        r[0] = a.x; r[1] = a.y; r[2] = a.z; r[3] = a.w;
        c[0] = d.x; c[1] = d.y; c[2] = d.z; c[3] = d.w;
    }
#pragma unroll
    for (int k = 0; k < 4; ++k) {
        int s = atomicAdd(&g_cnt[c[k]], 1);
        if (s < CAP) g_csr[c[k] * CAP + s] = r[k];
    }
}

// g1 = (x @ W1) * dinv.  16 rows per block, 256 threads = (16 j, 16 rows).
__global__ void k_gemm1(const float* __restrict__ x, const float* __restrict__ W1) {
    __shared__ float4 xs[512];      // 16 rows x 128 floats
    __shared__ float  ws[NF * NH];  // W1 [128][16], k-major (j fastest)

    int t  = threadIdx.x;
    int r0 = blockIdx.x * 16;       // 6250 * 16 = 100000 exactly

    const float4* xg = (const float4*)(x + (size_t)r0 * NF);
    xs[t]       = xg[t];
    xs[t + 256] = xg[t + 256];
#pragma unroll
    for (int i = 0; i < 8; ++i) ws[t + i * 256] = W1[t + i * 256];
    __syncthreads();

    int j  = t & 15;
    int ty = t >> 4;
    const float4* xr = xs + ty * 32;

    float acc = 0.0f;
#pragma unroll
    for (int kk = 0; kk < 32; ++kk) {
        float4 v = xr[kk];
        const float* wp = ws + kk * 64 + j;     // Ws[4kk..4kk+3][j]
        acc += v.x * wp[0] + v.y * wp[16] + v.z * wp[32] + v.w * wp[48];
    }
    int row = r0 + ty;
    float dv = rsqrtf((float)(g_cnt[row] + 1));
    g_g1[row * NH + j] = acc * dv;
}

// Layer-1 pull aggregation + fused node epilogue. One warp per node.
// Lanes: q = lane&3 (float4 component, j = 4q..4q+3), grp = lane>>2 (8 edge groups).
// Each quad gathers one edge's 64B g1 row as a single LDG.128; unroll-4 puts
// 4 gathers in flight per lane (deg ~ Poisson(32) -> one main iter covers
// nearly every node's edge list).
__global__ void k_pass1(const float* __restrict__ b1, const float* __restrict__ W2) {
    int warp = threadIdx.x >> 5;
    int lane = threadIdx.x & 31;
    int n = blockIdx.x * 8 + warp;              // 12500 * 8 = 100000 exactly
    int q   = lane & 3;
    int grp = lane >> 2;

    int deg  = g_cnt[n];
    int dcap = min(deg, CAP);
    const int* cs = g_csr + n * CAP;
    const float4* g1v = (const float4*)g_g1;

    float4 acc = make_float4(0.f, 0.f, 0.f, 0.f);
    int i = grp;
    for (; i + 24 < dcap; i += 32) {
        int r0 = __ldg(cs + i);
        int r1 = __ldg(cs + i + 8);
        int r2 = __ldg(cs + i + 16);
        int r3 = __ldg(cs + i + 24);
        float4 a = g1v[r0 * 4 + q];
        float4 b = g1v[r1 * 4 + q];
        float4 c = g1v[r2 * 4 + q];
        float4 d = g1v[r3 * 4 + q];
        acc.x += (a.x + b.x) + (c.x + d.x);
        acc.y += (a.y + b.y) + (c.y + d.y);
        acc.z += (a.z + b.z) + (c.z + d.z);
        acc.w += (a.w + b.w) + (c.w + d.w);
    }
    for (; i < dcap; i += 8) {
        int r0 = __ldg(cs + i);
        float4 a = g1v[r0 * 4 + q];
        acc.x += a.x; acc.y += a.y; acc.z += a.z; acc.w += a.w;
    }
    // merge the 8 edge groups (xor over lane bits 2..4)
#pragma unroll
    for (int m = 4; m <= 16; m <<= 1) {
        acc.x += __shfl_xor_sync(0xffffffffu, acc.x, m);
        acc.y += __shfl_xor_sync(0xffffffffu, acc.y, m);
        acc.z += __shfl_xor_sync(0xffffffffu, acc.z, m);
        acc.w += __shfl_xor_sync(0xffffffffu, acc.w, m);
    }

    float dv = rsqrtf((float)(deg + 1));
    float4 self = g1v[n * 4 + q];
    float4 bb = ((const float4*)b1)[q];
    float4 ww = ((const float4*)W2)[q];
    float h0 = fmaxf(fmaf(dv, acc.x + self.x, bb.x), 0.0f);
    float h1 = fmaxf(fmaf(dv, acc.y + self.y, bb.y), 0.0f);
    float h2 = fmaxf(fmaf(dv, acc.z + self.z, bb.z), 0.0f);
    float h3 = fmaxf(fmaf(dv, acc.w + self.w, bb.w), 0.0f);
    float p  = h0 * ww.x + h1 * ww.y + h2 * ww.z + h3 * ww.w;
    p += __shfl_xor_sync(0xffffffffu, p, 1);
    p += __shfl_xor_sync(0xffffffffu, p, 2);
    if (lane == 0) g_g2[n] = p * dv;
}

// Layer-2 pull aggregation + output. One warp per node, lane-per-edge,
// guarded 2-unroll for deg > 32 nodes.
__global__ void k_pass2(float* __restrict__ out, const float* __restrict__ b2) {
    int warp = threadIdx.x >> 5;
    int lane = threadIdx.x & 31;
    int n = blockIdx.x * 8 + warp;

    int deg  = g_cnt[n];
    int dcap = min(deg, CAP);
    const int* cs = g_csr + n * CAP;

    float s = 0.0f;
    int i = lane;
    for (; i + 32 < dcap; i += 64) {
        float v0 = g_g2[__ldg(cs + i)];
        float v1 = g_g2[__ldg(cs + i + 32)];
        s += v0 + v1;
    }
    for (; i < dcap; i += 32)
        s += g_g2[__ldg(cs + i)];
#pragma unroll
    for (int m = 16; m; m >>= 1)
        s += __shfl_xor_sync(0xffffffffu, s, m);

    if (lane == 0) {
        float dv = rsqrtf((float)(deg + 1));
        out[n] = fmaf(dv, s + g_g2[n], b2[0]);
    }
}

// ---------------- launch ----------------
extern "C" void kernel_launch(void* const* d_in, const int* in_sizes, int n_in,
                              void* d_out, int out_size) {
    const float* x   = (const float*)d_in[0];
    const void*  ei  = d_in[1];                 // edge_index [2, E], int32 or int64
    const float* W1  = (const float*)d_in[2];
    const float* b1  = (const float*)d_in[3];
    const float* W2  = (const float*)d_in[4];
    const float* b2  = (const float*)d_in[5];
    float* out       = (float*)d_out;

    void* cntp = nullptr;
    cudaGetSymbolAddress(&cntp, g_cnt);
    cudaMemsetAsync(cntp, 0, NN * sizeof(int));

    k_build <<<NE / 1024, 256>>>(ei);
    k_gemm1 <<<NN / 16, 256>>>(x, W1);
    k_pass1 <<<NN / 8, 256>>>(b1, W2);
    k_pass2 <<<NN / 8, 256>>>(out, b2);
}

// round 16
// speedup vs baseline: 1.0017x; 1.0017x over previous
#include <cuda_runtime.h>
#include <cstdint>

#define NN 100000
#define NE 3200000
#define NF 128
#define NH 16
#define CAP 128

// ---------------- scratch (static device memory; no allocations) ----------------
__device__ int   g_cnt[NN];            // in-degree / CSR fill counter
__device__ int   g_csr[NN * CAP];      // padded CSR: rows (sources) per dst node
__device__ float g_g1[NN * NH];        // g1 = (x@W1)*dinv   [N,16]
__device__ float g_g2[NN];             // g2 = (h1@W2)*dinv  [N]

// Build padded CSR keyed by destination; g_cnt becomes the in-degree.
// 4 edges per thread, vectorized index loads. Edge dtype (int32 vs int64)
// detected inline: high 32-bit words of the first 32 int64 slots are all zero
// iff the data is int64 (node ids < 100000; if int32, those words are random
// node ids -> P(all 32 == 0) ~ 1e-160).
__global__ void k_build(const void* __restrict__ ep) {
    int lane = threadIdx.x & 31;
    const unsigned int* e32 = (const unsigned int*)ep;
    int is64 = __all_sync(0xffffffffu, e32[2 * lane + 1] == 0u);

    int t = blockIdx.x * 256 + threadIdx.x;     // t in [0, NE/4)
    int r[4], c[4];
    if (is64) {
        const longlong2* p = (const longlong2*)ep;
        longlong2 a = __ldg(p + 2 * t);
        longlong2 b = __ldg(p + 2 * t + 1);
        longlong2 d = __ldg(p + (NE >> 1) + 2 * t);
        longlong2 e = __ldg(p + (NE >> 1) + 2 * t + 1);
        r[0] = (int)a.x; r[1] = (int)a.y; r[2] = (int)b.x; r[3] = (int)b.y;
        c[0] = (int)d.x; c[1] = (int)d.y; c[2] = (int)e.x; c[3] = (int)e.y;
    } else {
        const int4* p = (const int4*)ep;
        int4 a = __ldg(p + t);
        int4 d = __ldg(p + (NE >> 2) + t);
        r[0] = a.x; r[1] = a.y; r[2] = a.z; r[3] = a.w;
        c[0] = d.x; c[1] = d.y; c[2] = d.z; c[3] = d.w;
    }
#pragma unroll
    for (int k = 0; k < 4; ++k) {
        int s = atomicAdd(&g_cnt[c[k]], 1);
        if (s < CAP) g_csr[c[k] * CAP + s] = r[k];
    }
}

// g1 = (x @ W1) * dinv.  16 rows per block, 256 threads = (16 j, 16 rows).
__global__ void k_gemm1(const float* __restrict__ x, const float* __restrict__ W1) {
    __shared__ float4 xs[512];      // 16 rows x 128 floats
    __shared__ float  ws[NF * NH];  // W1 [128][16], k-major (j fastest)

    int t  = threadIdx.x;
    int r0 = blockIdx.x * 16;       // 6250 * 16 = 100000 exactly

    const float4* xg = (const float4*)(x + (size_t)r0 * NF);
    xs[t]       = xg[t];
    xs[t + 256] = xg[t + 256];
#pragma unroll
    for (int i = 0; i < 8; ++i) ws[t + i * 256] = W1[t + i * 256];
    __syncthreads();

    int j  = t & 15;
    int ty = t >> 4;
    const float4* xr = xs + ty * 32;

    float acc = 0.0f;
#pragma unroll
    for (int kk = 0; kk < 32; ++kk) {
        float4 v = xr[kk];
        const float* wp = ws + kk * 64 + j;     // Ws[4kk..4kk+3][j]
        acc += v.x * wp[0] + v.y * wp[16] + v.z * wp[32] + v.w * wp[48];
    }
    int row = r0 + ty;
    float dv = rsqrtf((float)(g_cnt[row] + 1));
    g_g1[row * NH + j] = acc * dv;
}

// Layer-1 pull aggregation + fused node epilogue. One warp per node.
// Lanes: q = lane&3 (float4 component, j = 4q..4q+3), grp = lane>>2 (8 edge groups).
// Each quad gathers one edge's 64B g1 row as a single LDG.128; unroll-4 puts
// 4 gathers in flight per lane (deg ~ Poisson(32) -> one main iter covers
// nearly every node's edge list).
__global__ void k_pass1(const float* __restrict__ b1, const float* __restrict__ W2) {
    int warp = threadIdx.x >> 5;
    int lane = threadIdx.x & 31;
    int n = blockIdx.x * 8 + warp;              // 12500 * 8 = 100000 exactly
    int q   = lane & 3;
    int grp = lane >> 2;

    int deg  = g_cnt[n];
    int dcap = min(deg, CAP);
    const int* cs = g_csr + n * CAP;
    const float4* g1v = (const float4*)g_g1;

    float4 acc = make_float4(0.f, 0.f, 0.f, 0.f);
    int i = grp;
    for (; i + 24 < dcap; i += 32) {
        int r0 = __ldg(cs + i);
        int r1 = __ldg(cs + i + 8);
        int r2 = __ldg(cs + i + 16);
        int r3 = __ldg(cs + i + 24);
        float4 a = g1v[r0 * 4 + q];
        float4 b = g1v[r1 * 4 + q];
        float4 c = g1v[r2 * 4 + q];
        float4 d = g1v[r3 * 4 + q];
        acc.x += (a.x + b.x) + (c.x + d.x);
        acc.y += (a.y + b.y) + (c.y + d.y);
        acc.z += (a.z + b.z) + (c.z + d.z);
        acc.w += (a.w + b.w) + (c.w + d.w);
    }
    for (; i < dcap; i += 8) {
        int r0 = __ldg(cs + i);
        float4 a = g1v[r0 * 4 + q];
        acc.x += a.x; acc.y += a.y; acc.z += a.z; acc.w += a.w;
    }
    // merge the 8 edge groups (xor over lane bits 2..4)
#pragma unroll
    for (int m = 4; m <= 16; m <<= 1) {
        acc.x += __shfl_xor_sync(0xffffffffu, acc.x, m);
        acc.y += __shfl_xor_sync(0xffffffffu, acc.y, m);
        acc.z += __shfl_xor_sync(0xffffffffu, acc.z, m);
        acc.w += __shfl_xor_sync(0xffffffffu, acc.w, m);
    }

    float dv = rsqrtf((float)(deg + 1));
    float4 self = g1v[n * 4 + q];
    float4 bb = ((const float4*)b1)[q];
    float4 ww = ((const float4*)W2)[q];
    float h0 = fmaxf(fmaf(dv, acc.x + self.x, bb.x), 0.0f);
    float h1 = fmaxf(fmaf(dv, acc.y + self.y, bb.y), 0.0f);
    float h2 = fmaxf(fmaf(dv, acc.z + self.z, bb.z), 0.0f);
    float h3 = fmaxf(fmaf(dv, acc.w + self.w, bb.w), 0.0f);
    float p  = h0 * ww.x + h1 * ww.y + h2 * ww.z + h3 * ww.w;
    p += __shfl_xor_sync(0xffffffffu, p, 1);
    p += __shfl_xor_sync(0xffffffffu, p, 2);
    if (lane == 0) g_g2[n] = p * dv;
}

// Layer-2 pull aggregation + output. One warp per node, lane-per-edge,
// guarded 2-unroll for deg > 32 nodes.
__global__ void k_pass2(float* __restrict__ out, const float* __restrict__ b2) {
    int warp = threadIdx.x >> 5;
    int lane = threadIdx.x & 31;
    int n = blockIdx.x * 8 + warp;

    int deg  = g_cnt[n];
    int dcap = min(deg, CAP);
    const int* cs = g_csr + n * CAP;

    float s = 0.0f;
    int i = lane;
    for (; i + 32 < dcap; i += 64) {
        float v0 = g_g2[__ldg(cs + i)];
        float v1 = g_g2[__ldg(cs + i + 32)];
        s += v0 + v1;
    }
    for (; i < dcap; i += 32)
        s += g_g2[__ldg(cs + i)];
#pragma unroll
    for (int m = 16; m; m >>= 1)
        s += __shfl_xor_sync(0xffffffffu, s, m);

    if (lane == 0) {
        float dv = rsqrtf((float)(deg + 1));
        out[n] = fmaf(dv, s + g_g2[n], b2[0]);
    }
}

// ---------------- launch ----------------
extern "C" void kernel_launch(void* const* d_in, const int* in_sizes, int n_in,
                              void* d_out, int out_size) {
    const float* x   = (const float*)d_in[0];
    const void*  ei  = d_in[1];                 // edge_index [2, E], int32 or int64
    const float* W1  = (const float*)d_in[2];
    const float* b1  = (const float*)d_in[3];
    const float* W2  = (const float*)d_in[4];
    const float* b2  = (const float*)d_in[5];
    float* out       = (float*)d_out;

    void* cntp = nullptr;
    cudaGetSymbolAddress(&cntp, g_cnt);
    cudaMemsetAsync(cntp, 0, NN * sizeof(int));

    k_build <<<NE / 1024, 256>>>(ei);
    k_gemm1 <<<NN / 16, 256>>>(x, W1);
    k_pass1 <<<NN / 8, 256>>>(b1, W2);
    k_pass2 <<<NN / 8, 256>>>(out, b2);
}

// round 17
// speedup vs baseline: 1.0318x; 1.0301x over previous
#include <cuda_runtime.h>
#include <cstdint>

#define NN 100000
#define NE 3200000
#define NF 128
#define NH 16
#define CAP 128

// ---------------- scratch (static device memory; no allocations) ----------------
__device__ int   g_cnt[NN];            // in-degree / CSR fill counter
__device__ int   g_csr[NN * CAP];      // padded CSR: rows (sources) per dst node
__device__ float g_g1[NN * NH];        // g1 = (x@W1)*dinv   [N,16]
__device__ float g_g2[NN];             // g2 = (h1@W2)*dinv  [N]

// Build padded CSR keyed by destination; g_cnt becomes the in-degree.
// 4 edges per thread, vectorized index loads. Edge dtype (int32 vs int64)
// detected inline: high 32-bit words of the first 32 int64 slots are all zero
// iff the data is int64 (node ids < 100000; if int32, those words are random
// node ids -> P(all 32 == 0) ~ 1e-160).
__global__ void k_build(const void* __restrict__ ep) {
    int lane = threadIdx.x & 31;
    const unsigned int* e32 = (const unsigned int*)ep;
    int is64 = __all_sync(0xffffffffu, e32[2 * lane + 1] == 0u);

    int t = blockIdx.x * 256 + threadIdx.x;     // t in [0, NE/4)
    int r[4], c[4];
    if (is64) {
        const longlong2* p = (const longlong2*)ep;
        longlong2 a = __ldg(p + 2 * t);
        longlong2 b = __ldg(p + 2 * t + 1);
        longlong2 d = __ldg(p + (NE >> 1) + 2 * t);
        longlong2 e = __ldg(p + (NE >> 1) + 2 * t + 1);
        r[0] = (int)a.x; r[1] = (int)a.y; r[2] = (int)b.x; r[3] = (int)b.y;
        c[0] = (int)d.x; c[1] = (int)d.y; c[2] = (int)e.x; c[3] = (int)e.y;
    } else {
        const int4* p = (const int4*)ep;
        int4 a = __ldg(p + t);
        int4 d = __ldg(p + (NE >> 2) + t);
        r[0] = a.x; r[1] = a.y; r[2] = a.z; r[3] = a.w;
        c[0] = d.x; c[1] = d.y; c[2] = d.z; c[3] = d.w;
    }
#pragma unroll
    for (int k = 0; k < 4; ++k) {
        int s = atomicAdd(&g_cnt[c[k]], 1);
        if (s < CAP) g_csr[c[k] * CAP + s] = r[k];
    }
}

// g1 = (x @ W1) * dinv.  16 rows per block, 256 threads = (16 j, 16 rows).
__global__ void k_gemm1(const float* __restrict__ x, const float* __restrict__ W1) {
    __shared__ float4 xs[512];      // 16 rows x 128 floats
    __shared__ float  ws[NF * NH];  // W1 [128][16], k-major (j fastest)

    int t  = threadIdx.x;
    int r0 = blockIdx.x * 16;       // 6250 * 16 = 100000 exactly

    const float4* xg = (const float4*)(x + (size_t)r0 * NF);
    xs[t]       = xg[t];
    xs[t + 256] = xg[t + 256];
#pragma unroll
    for (int i = 0; i < 8; ++i) ws[t + i * 256] = W1[t + i * 256];
    __syncthreads();

    int j  = t & 15;
    int ty = t >> 4;
    const float4* xr = xs + ty * 32;

    float acc = 0.0f;
#pragma unroll
    for (int kk = 0; kk < 32; ++kk) {
        float4 v = xr[kk];
        const float* wp = ws + kk * 64 + j;     // Ws[4kk..4kk+3][j]
        acc += v.x * wp[0] + v.y * wp[16] + v.z * wp[32] + v.w * wp[48];
    }
    int row = r0 + ty;
    float dv = rsqrtf((float)(g_cnt[row] + 1));
    g_g1[row * NH + j] = acc * dv;
}

// Layer-1 pull aggregation + fused node epilogue. One warp per node.
// Lanes: q = lane&3 (float4 component, j = 4q..4q+3), grp = lane>>2 (8 edge groups).
// Each quad gathers one edge's 64B g1 row as a single LDG.128; unroll-4 puts
// 4 gathers in flight per lane.
__global__ void k_pass1(const float* __restrict__ b1, const float* __restrict__ W2) {
    int warp = threadIdx.x >> 5;
    int lane = threadIdx.x & 31;
    int n = blockIdx.x * 8 + warp;              // 12500 * 8 = 100000 exactly
    int q   = lane & 3;
    int grp = lane >> 2;

    int deg  = g_cnt[n];
    int dcap = min(deg, CAP);
    const int* cs = g_csr + n * CAP;
    const float4* g1v = (const float4*)g_g1;

    float4 acc = make_float4(0.f, 0.f, 0.f, 0.f);
    int i = grp;
    for (; i + 24 < dcap; i += 32) {
        int r0 = __ldg(cs + i);
        int r1 = __ldg(cs + i + 8);
        int r2 = __ldg(cs + i + 16);
        int r3 = __ldg(cs + i + 24);
        float4 a = g1v[r0 * 4 + q];
        float4 b = g1v[r1 * 4 + q];
        float4 c = g1v[r2 * 4 + q];
        float4 d = g1v[r3 * 4 + q];
        acc.x += (a.x + b.x) + (c.x + d.x);
        acc.y += (a.y + b.y) + (c.y + d.y);
        acc.z += (a.z + b.z) + (c.z + d.z);
        acc.w += (a.w + b.w) + (c.w + d.w);
    }
    for (; i < dcap; i += 8) {
        int r0 = __ldg(cs + i);
        float4 a = g1v[r0 * 4 + q];
        acc.x += a.x; acc.y += a.y; acc.z += a.z; acc.w += a.w;
    }
    // merge the 8 edge groups (xor over lane bits 2..4)
#pragma unroll
    for (int m = 4; m <= 16; m <<= 1) {
        acc.x += __shfl_xor_sync(0xffffffffu, acc.x, m);
        acc.y += __shfl_xor_sync(0xffffffffu, acc.y, m);
        acc.z += __shfl_xor_sync(0xffffffffu, acc.z, m);
        acc.w += __shfl_xor_sync(0xffffffffu, acc.w, m);
    }

    float dv = rsqrtf((float)(deg + 1));
    float4 self = g1v[n * 4 + q];
    float4 bb = ((const float4*)b1)[q];
    float4 ww = ((const float4*)W2)[q];
    float h0 = fmaxf(fmaf(dv, acc.x + self.x, bb.x), 0.0f);
    float h1 = fmaxf(fmaf(dv, acc.y + self.y, bb.y), 0.0f);
    float h2 = fmaxf(fmaf(dv, acc.z + self.z, bb.z), 0.0f);
    float h3 = fmaxf(fmaf(dv, acc.w + self.w, bb.w), 0.0f);
    float p  = h0 * ww.x + h1 * ww.y + h2 * ww.z + h3 * ww.w;
    p += __shfl_xor_sync(0xffffffffu, p, 1);
    p += __shfl_xor_sync(0xffffffffu, p, 2);
    if (lane == 0) g_g2[n] = p * dv;
}

// Layer-2 pull aggregation + output. 8 lanes per node, 4 nodes per warp.
// Each lane owns ~deg/8 ~ 4 edges; unroll-4 puts 4 gathers in flight per lane
// (vs MLP=1 with the old lane-per-edge layout).
__global__ void k_pass2(float* __restrict__ out, const float* __restrict__ b2) {
    int lane = threadIdx.x & 31;
    int sub  = lane & 7;                        // lane within the 8-lane node group
    int n = blockIdx.x * 32 + ((threadIdx.x >> 3) & ~0);  // 3125 * 32 = 100000
    n = blockIdx.x * 32 + (threadIdx.x >> 3) - ((threadIdx.x >> 3) & 0); // simplify below
    n = blockIdx.x * 32 + (threadIdx.x >> 3);   // 32 node-groups per 256-thread block

    int deg  = g_cnt[n];
    int dcap = min(deg, CAP);
    const int* cs = g_csr + n * CAP;

    float s = 0.0f;
    int i = sub;
    for (; i + 24 < dcap; i += 32) {
        int r0 = __ldg(cs + i);
        int r1 = __ldg(cs + i + 8);
        int r2 = __ldg(cs + i + 16);
        int r3 = __ldg(cs + i + 24);
        float v0 = g_g2[r0];
        float v1 = g_g2[r1];
        float v2 = g_g2[r2];
        float v3 = g_g2[r3];
        s += (v0 + v1) + (v2 + v3);
    }
    for (; i < dcap; i += 8)
        s += g_g2[__ldg(cs + i)];
    // reduce over the 8-lane group (xor 1,2,4 stays within the group)
    s += __shfl_xor_sync(0xffffffffu, s, 1);
    s += __shfl_xor_sync(0xffffffffu, s, 2);
    s += __shfl_xor_sync(0xffffffffu, s, 4);

    if (sub == 0) {
        float dv = rsqrtf((float)(deg + 1));
        out[n] = fmaf(dv, s + g_g2[n], b2[0]);
    }
}

// ---------------- launch ----------------
extern "C" void kernel_launch(void* const* d_in, const int* in_sizes, int n_in,
                              void* d_out, int out_size) {
    const float* x   = (const float*)d_in[0];
    const void*  ei  = d_in[1];                 // edge_index [2, E], int32 or int64
    const float* W1  = (const float*)d_in[2];
    const float* b1  = (const float*)d_in[3];
    const float* W2  = (const float*)d_in[4];
    const float* b2  = (const float*)d_in[5];
    float* out       = (float*)d_out;

    void* cntp = nullptr;
    cudaGetSymbolAddress(&cntp, g_cnt);
    cudaMemsetAsync(cntp, 0, NN * sizeof(int));

    k_build <<<NE / 1024, 256>>>(ei);
    k_gemm1 <<<NN / 16, 256>>>(x, W1);
    k_pass1 <<<NN / 8, 256>>>(b1, W2);
    k_pass2 <<<NN / 32, 256>>>(out, b2);
}